// round 3
// baseline (speedup 1.0000x reference)
#include <cuda_runtime.h>
#include <cuda_bf16.h>

#define N_NODES 50000
#define N_EDGES 800000
#define F_IN    128
#define HIDDEN  256
#define N_GRAPHS 128

// ---------------- scratch (device globals; no allocation allowed) ----------
__device__ float g_bufA[(size_t)N_NODES * HIDDEN];   // 51.2 MB
__device__ float g_bufB[(size_t)N_NODES * HIDDEN];   // 51.2 MB
__device__ float g_pool[N_GRAPHS * HIDDEN];
__device__ int   g_rowptr[N_NODES + 1];
__device__ int   g_fill[N_NODES];
__device__ int   g_csr_src[N_EDGES];
__device__ float g_csr_w[N_EDGES];

// ---------------- CSR build -------------------------------------------------
__global__ void zero_rowptr_kernel() {
    int i = blockIdx.x * blockDim.x + threadIdx.x;
    if (i <= N_NODES) g_rowptr[i] = 0;
}

__global__ void count_kernel(const int* __restrict__ edst) {
    int e = blockIdx.x * blockDim.x + threadIdx.x;
    if (e < N_EDGES) atomicAdd(&g_rowptr[edst[e] + 1], 1);
}

// single-block inclusive scan over g_rowptr[1..N_NODES] (rowptr[0] stays 0)
__global__ void scan_kernel() {
    __shared__ int warpsums[32];
    __shared__ int carry;
    int tid = threadIdx.x, lane = tid & 31, wid = tid >> 5;
    if (tid == 0) carry = 0;
    __syncthreads();
    for (int base = 1; base <= N_NODES; base += 1024) {
        int i = base + tid;
        int v = (i <= N_NODES) ? g_rowptr[i] : 0;
        int x = v;
        #pragma unroll
        for (int off = 1; off < 32; off <<= 1) {
            int y = __shfl_up_sync(0xffffffffu, x, off);
            if (lane >= off) x += y;
        }
        if (lane == 31) warpsums[wid] = x;
        __syncthreads();
        if (wid == 0) {
            int s = warpsums[lane];
            #pragma unroll
            for (int off = 1; off < 32; off <<= 1) {
                int y = __shfl_up_sync(0xffffffffu, s, off);
                if (lane >= off) s += y;
            }
            warpsums[lane] = s;
        }
        __syncthreads();
        int prefix = carry + x + (wid ? warpsums[wid - 1] : 0);
        int total  = warpsums[31];
        if (i <= N_NODES) g_rowptr[i] = prefix;
        __syncthreads();
        if (tid == 0) carry += total;
        __syncthreads();
    }
}

__global__ void fill_init_kernel() {
    int i = blockIdx.x * blockDim.x + threadIdx.x;
    if (i < N_NODES) g_fill[i] = g_rowptr[i];
}

__global__ void scatter_kernel(const int* __restrict__ esrc,
                               const int* __restrict__ edst,
                               const float* __restrict__ ew) {
    int e = blockIdx.x * blockDim.x + threadIdx.x;
    if (e < N_EDGES) {
        int slot = atomicAdd(&g_fill[edst[e]], 1);
        g_csr_src[slot] = esrc[e];
        g_csr_w[slot]   = ew[e];
    }
}

// ---------------- GEMM: C[M,N] = A[M,K] @ B[K,N], fp32 ---------------------
#define GBM 128
#define GBN 64
#define GBK 16

__global__ __launch_bounds__(256)
void gemm_kernel(const float* __restrict__ A, const float* __restrict__ B,
                 float* __restrict__ C, int M, int N, int K) {
    __shared__ float As[GBK][GBM];
    __shared__ float Bs[GBK][GBN];
    int tid = threadIdx.x;
    int tx = tid & 15;   // col group (TN=4)
    int ty = tid >> 4;   // row group (TM=8)
    int row0 = blockIdx.y * GBM;
    int col0 = blockIdx.x * GBN;

    float acc[8][4];
    #pragma unroll
    for (int m = 0; m < 8; m++)
        #pragma unroll
        for (int n = 0; n < 4; n++) acc[m][n] = 0.f;

    for (int kt = 0; kt < K; kt += GBK) {
        // A tile: 128x16 = 512 float4; 2 per thread; store transposed
        #pragma unroll
        for (int q = 0; q < 2; q++) {
            int f  = tid * 2 + q;
            int r  = f >> 2;
            int kv = f & 3;
            float4 av = make_float4(0.f, 0.f, 0.f, 0.f);
            int grow = row0 + r;
            if (grow < M)
                av = *reinterpret_cast<const float4*>(&A[(size_t)grow * K + kt + kv * 4]);
            As[kv * 4 + 0][r] = av.x;
            As[kv * 4 + 1][r] = av.y;
            As[kv * 4 + 2][r] = av.z;
            As[kv * 4 + 3][r] = av.w;
        }
        // B tile: 16x64 = 256 float4; 1 per thread
        {
            int kb = tid >> 4;
            int nv = tid & 15;
            float4 bv = *reinterpret_cast<const float4*>(
                &B[(size_t)(kt + kb) * N + col0 + nv * 4]);
            *reinterpret_cast<float4*>(&Bs[kb][nv * 4]) = bv;
        }
        __syncthreads();
        #pragma unroll
        for (int kk = 0; kk < GBK; kk++) {
            float a[8];
            #pragma unroll
            for (int m = 0; m < 8; m++) a[m] = As[kk][ty * 8 + m];
            float4 bv = *reinterpret_cast<const float4*>(&Bs[kk][tx * 4]);
            float b[4] = {bv.x, bv.y, bv.z, bv.w};
            #pragma unroll
            for (int m = 0; m < 8; m++)
                #pragma unroll
                for (int n = 0; n < 4; n++) acc[m][n] += a[m] * b[n];
        }
        __syncthreads();
    }
    #pragma unroll
    for (int m = 0; m < 8; m++) {
        int grow = row0 + ty * 8 + m;
        if (grow < M) {
            float4 cv = make_float4(acc[m][0], acc[m][1], acc[m][2], acc[m][3]);
            *reinterpret_cast<float4*>(&C[(size_t)grow * N + col0 + tx * 4]) = cv;
        }
    }
}

// ---------------- SPMM + bias + relu: one block per dst node ----------------
__global__ __launch_bounds__(HIDDEN)
void spmm_bias_relu_kernel(const float* __restrict__ t,
                           const float* __restrict__ bias,
                           float* __restrict__ out) {
    __shared__ int   s_src[64];
    __shared__ float s_w[64];
    int node = blockIdx.x;
    int tid = threadIdx.x;
    int start = g_rowptr[node];
    int end   = g_rowptr[node + 1];
    float acc = 0.f;
    for (int base = start; base < end; base += 64) {
        int cnt = min(64, end - base);
        if (tid < cnt) {
            s_src[tid] = g_csr_src[base + tid];
            s_w[tid]   = g_csr_w[base + tid];
        }
        __syncthreads();
        for (int i = 0; i < cnt; i++)
            acc += t[(size_t)s_src[i] * HIDDEN + tid] * s_w[i];
        __syncthreads();
    }
    out[(size_t)node * HIDDEN + tid] = fmaxf(acc + bias[tid], 0.f);
}

// ---------------- segment pool (seg_ids are sorted) -------------------------
__global__ __launch_bounds__(HIDDEN)
void pool_kernel(const float* __restrict__ h, const int* __restrict__ seg) {
    int gi = blockIdx.x, tid = threadIdx.x;
    int lo = 0, hi = N_NODES;
    while (lo < hi) { int mid = (lo + hi) >> 1; if (seg[mid] < gi) lo = mid + 1; else hi = mid; }
    int start = lo;
    hi = N_NODES;
    while (lo < hi) { int mid = (lo + hi) >> 1; if (seg[mid] < gi + 1) lo = mid + 1; else hi = mid; }
    int end = lo;
    float acc = 0.f;
    for (int i = start; i < end; i++)
        acc += h[(size_t)i * HIDDEN + tid];
    g_pool[gi * HIDDEN + tid] = acc;
}

// ---------------- dense head: out[g] = relu(pool@Wd+bd) @ Wo + bo -----------
__global__ __launch_bounds__(HIDDEN)
void head_kernel(const float* __restrict__ Wd, const float* __restrict__ bd,
                 const float* __restrict__ Wo, const float* __restrict__ bo,
                 float* __restrict__ out) {
    __shared__ float s_g[HIDDEN];
    __shared__ float s_red[HIDDEN];
    int gi = blockIdx.x, j = threadIdx.x;
    s_g[j] = g_pool[gi * HIDDEN + j];
    __syncthreads();
    float acc = bd[j];
    #pragma unroll 8
    for (int k = 0; k < HIDDEN; k++)
        acc += s_g[k] * Wd[k * HIDDEN + j];
    acc = fmaxf(acc, 0.f);
    s_red[j] = acc * Wo[j];
    __syncthreads();
    for (int s = HIDDEN / 2; s > 0; s >>= 1) {
        if (j < s) s_red[j] += s_red[j + s];
        __syncthreads();
    }
    if (j == 0) out[gi] = s_red[0] + bo[0];
}

// ---------------- launch ----------------------------------------------------
extern "C" void kernel_launch(void* const* d_in, const int* in_sizes, int n_in,
                              void* d_out, int out_size) {
    const float* x    = (const float*)d_in[0];
    const int*   esrc = (const int*)  d_in[1];
    const int*   edst = (const int*)  d_in[2];
    const float* ew   = (const float*)d_in[3];
    const int*   seg  = (const int*)  d_in[4];
    const float* W1   = (const float*)d_in[5];
    const float* b1   = (const float*)d_in[6];
    const float* W2   = (const float*)d_in[7];
    const float* b2   = (const float*)d_in[8];
    const float* Wd   = (const float*)d_in[9];
    const float* bd   = (const float*)d_in[10];
    const float* Wo   = (const float*)d_in[11];
    const float* bo   = (const float*)d_in[12];
    float* out = (float*)d_out;

    // device-global pointers (same TU; kernels reference the symbols directly)
    float* bufA; cudaGetSymbolAddress((void**)&bufA, g_bufA);
    float* bufB; cudaGetSymbolAddress((void**)&bufB, g_bufB);

    // --- CSR build (by destination) ---
    zero_rowptr_kernel<<<(N_NODES + 256) / 256, 256>>>();
    count_kernel<<<(N_EDGES + 255) / 256, 256>>>(edst);
    scan_kernel<<<1, 1024>>>();
    fill_init_kernel<<<(N_NODES + 255) / 256, 256>>>();
    scatter_kernel<<<(N_EDGES + 255) / 256, 256>>>(esrc, edst, ew);

    // --- layer 1: t0 = x @ W1 ; h1 = relu(spmm(t0) + b1) ---
    {
        dim3 grid(HIDDEN / GBN, (N_NODES + GBM - 1) / GBM);
        gemm_kernel<<<grid, 256>>>(x, W1, bufA, N_NODES, HIDDEN, F_IN);
    }
    spmm_bias_relu_kernel<<<N_NODES, HIDDEN>>>(bufA, b1, bufB);

    // --- layer 2: t1 = h1 @ W2 ; h2 = relu(spmm(t1) + b2) ---
    {
        dim3 grid(HIDDEN / GBN, (N_NODES + GBM - 1) / GBM);
        gemm_kernel<<<grid, 256>>>(bufB, W2, bufA, N_NODES, HIDDEN, HIDDEN);
    }
    spmm_bias_relu_kernel<<<N_NODES, HIDDEN>>>(bufA, b2, bufB);

    // --- pool + head ---
    pool_kernel<<<N_GRAPHS, HIDDEN>>>(bufB, seg);
    head_kernel<<<N_GRAPHS, HIDDEN>>>(Wd, bd, Wo, bo, out);
}

// round 9
// speedup vs baseline: 1.3369x; 1.3369x over previous
#include <cuda_runtime.h>
#include <cuda_bf16.h>
#include <cstdint>

#define N_NODES 50000
#define N_EDGES 800000
#define F_IN    128
#define HIDDEN  256
#define N_GRAPHS 128

// ---------------- scratch (device globals; no allocation allowed) ----------
__device__ float g_bufA[(size_t)N_NODES * HIDDEN];   // 51.2 MB
__device__ float g_bufB[(size_t)N_NODES * HIDDEN];   // 51.2 MB
__device__ float g_pool[N_GRAPHS * HIDDEN];
__device__ float g_Wt1[HIDDEN * F_IN];               // W1^T : [256][128]
__device__ float g_Wt2[HIDDEN * HIDDEN];             // W2^T : [256][256]
__device__ int   g_rowptr[N_NODES + 1];
__device__ int   g_fill[N_NODES];
__device__ int   g_csr_src[N_EDGES];
__device__ float g_csr_w[N_EDGES];

// ---------------- helpers ---------------------------------------------------
__device__ __forceinline__ uint32_t f32_to_tf32(float v) {
    uint32_t o;
    asm("cvt.rna.tf32.f32 %0, %1;" : "=r"(o) : "f"(v));
    return o;
}

// XOR swizzle inside a 32-word (BK) row: conflict-free for both fragment halves
__device__ __forceinline__ int swz(int r, int c) {
    return r * 32 + (c ^ ((r & 7) << 2));
}

__device__ __forceinline__ void mma_tf32(float* c, const uint32_t* a, const uint32_t* b) {
    asm volatile(
        "mma.sync.aligned.m16n8k8.row.col.f32.tf32.tf32.f32 "
        "{%0,%1,%2,%3}, {%4,%5,%6,%7}, {%8,%9}, {%0,%1,%2,%3};"
        : "+f"(c[0]), "+f"(c[1]), "+f"(c[2]), "+f"(c[3])
        : "r"(a[0]), "r"(a[1]), "r"(a[2]), "r"(a[3]), "r"(b[0]), "r"(b[1]));
}

// ---------------- CSR build -------------------------------------------------
__global__ void zero_rowptr_kernel() {
    int i = blockIdx.x * blockDim.x + threadIdx.x;
    if (i <= N_NODES) g_rowptr[i] = 0;
}

__global__ void count_kernel(const int* __restrict__ edst) {
    int e = blockIdx.x * blockDim.x + threadIdx.x;
    if (e < N_EDGES) atomicAdd(&g_rowptr[edst[e] + 1], 1);
}

// single-block inclusive scan over g_rowptr[1..N_NODES]
__global__ void scan_kernel() {
    __shared__ int warpsums[32];
    __shared__ int carry;
    int tid = threadIdx.x, lane = tid & 31, wid = tid >> 5;
    if (tid == 0) carry = 0;
    __syncthreads();
    for (int base = 1; base <= N_NODES; base += 1024) {
        int i = base + tid;
        int v = (i <= N_NODES) ? g_rowptr[i] : 0;
        int x = v;
        #pragma unroll
        for (int off = 1; off < 32; off <<= 1) {
            int y = __shfl_up_sync(0xffffffffu, x, off);
            if (lane >= off) x += y;
        }
        if (lane == 31) warpsums[wid] = x;
        __syncthreads();
        if (wid == 0) {
            int s = warpsums[lane];
            #pragma unroll
            for (int off = 1; off < 32; off <<= 1) {
                int y = __shfl_up_sync(0xffffffffu, s, off);
                if (lane >= off) s += y;
            }
            warpsums[lane] = s;
        }
        __syncthreads();
        int prefix = carry + x + (wid ? warpsums[wid - 1] : 0);
        int total  = warpsums[31];
        if (i <= N_NODES) g_rowptr[i] = prefix;
        __syncthreads();
        if (tid == 0) carry += total;
        __syncthreads();
    }
}

__global__ void fill_init_kernel() {
    int i = blockIdx.x * blockDim.x + threadIdx.x;
    if (i < N_NODES) g_fill[i] = g_rowptr[i];
}

__global__ void scatter_kernel(const int* __restrict__ esrc,
                               const int* __restrict__ edst,
                               const float* __restrict__ ew) {
    int e = blockIdx.x * blockDim.x + threadIdx.x;
    if (e < N_EDGES) {
        int slot = atomicAdd(&g_fill[edst[e]], 1);
        g_csr_src[slot] = esrc[e];
        g_csr_w[slot]   = ew[e];
    }
}

// ---------------- weight transpose: Wt[n][k] = W[k][n] ----------------------
__global__ void transpose_kernel(const float* __restrict__ W, float* __restrict__ Wt,
                                 int K, int N) {
    __shared__ float tile[32][33];
    int bx = blockIdx.x * 32, by = blockIdx.y * 32;
    int x = bx + threadIdx.x;
    int y = by + threadIdx.y;
    #pragma unroll
    for (int j = 0; j < 32; j += 8)
        if (y + j < K && x < N) tile[threadIdx.y + j][threadIdx.x] = W[(y + j) * N + x];
    __syncthreads();
    x = by + threadIdx.x;
    y = bx + threadIdx.y;
    #pragma unroll
    for (int j = 0; j < 32; j += 8)
        if (y + j < N && x < K) Wt[(y + j) * K + x] = tile[threadIdx.x][threadIdx.y + j];
}

// ---------------- tf32 mma.sync GEMM: C = relu(A @ Bt^T + bias) -------------
// A: [M, KTOT] fp32 row-major. Bt: [256, KTOT] (output-col-major, K contiguous).
// CTA: BM=128 x BN=64, BK=32, 256 threads = 8 warps (4 M x 2 N), warp tile 32x32.
// Double-buffered smem (2 x (16KB A + 8KB B) = 48KB dynamic), reg prefetch.
template<int KTOT, bool RELU>
__global__ __launch_bounds__(256)
void mma_gemm_kernel(const float* __restrict__ A,
                     const float* __restrict__ Bt,
                     const float* __restrict__ bias,
                     float* __restrict__ C, int M) {
    extern __shared__ uint32_t smem_dyn[];
    uint32_t* sA[2] = { smem_dyn,             smem_dyn + 128 * 32 };
    uint32_t* sB[2] = { smem_dyn + 2*128*32,  smem_dyn + 2*128*32 + 64 * 32 };

    const int tid = threadIdx.x;
    const int lane = tid & 31, wid = tid >> 5;
    const int warp_m = wid & 3, warp_n = wid >> 2;
    const int row0 = blockIdx.y * 128;
    const int col0 = blockIdx.x * 64;

    float acc[2][4][4];
    #pragma unroll
    for (int i = 0; i < 2; i++)
        #pragma unroll
        for (int j = 0; j < 4; j++)
            #pragma unroll
            for (int k = 0; k < 4; k++) acc[i][j][k] = 0.f;

    const int NT = KTOT / 32;
    float4 rgA[4];   // 128x32 tile: 1024 float4, 4/thread
    float4 rgB[2];   // 64x32 tile:   512 float4, 2/thread

    // tile load (global -> regs)
    auto ldg_tile = [&](int t) {
        #pragma unroll
        for (int q = 0; q < 4; q++) {
            int f = tid + q * 256;
            int r = f >> 3, c4 = f & 7;
            float4 v = make_float4(0.f, 0.f, 0.f, 0.f);
            if (row0 + r < M)
                v = *reinterpret_cast<const float4*>(
                        &A[(size_t)(row0 + r) * KTOT + t * 32 + c4 * 4]);
            rgA[q] = v;
        }
        #pragma unroll
        for (int q = 0; q < 2; q++) {
            int f = tid + q * 256;
            int r = f >> 3, c4 = f & 7;
            rgB[q] = *reinterpret_cast<const float4*>(
                        &Bt[(size_t)(col0 + r) * KTOT + t * 32 + c4 * 4]);
        }
    };
    // regs -> smem (with tf32 rounding + swizzle)
    auto sts_tile = [&](int s) {
        #pragma unroll
        for (int q = 0; q < 4; q++) {
            int f = tid + q * 256;
            int r = f >> 3, c4 = f & 7;
            uint32_t* p = &sA[s][swz(r, c4 * 4)];
            p[0] = f32_to_tf32(rgA[q].x); p[1] = f32_to_tf32(rgA[q].y);
            p[2] = f32_to_tf32(rgA[q].z); p[3] = f32_to_tf32(rgA[q].w);
        }
        #pragma unroll
        for (int q = 0; q < 2; q++) {
            int f = tid + q * 256;
            int r = f >> 3, c4 = f & 7;
            uint32_t* p = &sB[s][swz(r, c4 * 4)];
            p[0] = f32_to_tf32(rgB[q].x); p[1] = f32_to_tf32(rgB[q].y);
            p[2] = f32_to_tf32(rgB[q].z); p[3] = f32_to_tf32(rgB[q].w);
        }
    };

    ldg_tile(0);
    sts_tile(0);
    __syncthreads();

    for (int t = 0; t < NT; t++) {
        if (t + 1 < NT) ldg_tile(t + 1);
        const uint32_t* cA = sA[t & 1];
        const uint32_t* cB = sB[t & 1];
        const int g = lane >> 2, q = lane & 3;
        #pragma unroll
        for (int kk = 0; kk < 4; kk++) {
            uint32_t af[2][4];
            #pragma unroll
            for (int mf = 0; mf < 2; mf++) {
                int r = warp_m * 32 + mf * 16 + g;
                int c = kk * 8 + q;
                af[mf][0] = cA[swz(r,     c)];
                af[mf][1] = cA[swz(r + 8, c)];
                af[mf][2] = cA[swz(r,     c + 4)];
                af[mf][3] = cA[swz(r + 8, c + 4)];
            }
            uint32_t bf[4][2];
            #pragma unroll
            for (int nf = 0; nf < 4; nf++) {
                int r = warp_n * 32 + nf * 8 + g;
                int c = kk * 8 + q;
                bf[nf][0] = cB[swz(r, c)];
                bf[nf][1] = cB[swz(r, c + 4)];
            }
            #pragma unroll
            for (int mf = 0; mf < 2; mf++)
                #pragma unroll
                for (int nf = 0; nf < 4; nf++)
                    mma_tf32(acc[mf][nf], af[mf], bf[nf]);
        }
        if (t + 1 < NT) sts_tile((t + 1) & 1);
        __syncthreads();
    }

    // epilogue: bias + optional relu, float2 stores
    const int g = lane >> 2, q = lane & 3;
    #pragma unroll
    for (int mf = 0; mf < 2; mf++) {
        #pragma unroll
        for (int half = 0; half < 2; half++) {
            int grow = row0 + warp_m * 32 + mf * 16 + half * 8 + g;
            if (grow >= M) continue;
            #pragma unroll
            for (int nf = 0; nf < 4; nf++) {
                int gcol = col0 + warp_n * 32 + nf * 8 + 2 * q;
                float v0 = acc[mf][nf][half * 2 + 0] + __ldg(&bias[gcol]);
                float v1 = acc[mf][nf][half * 2 + 1] + __ldg(&bias[gcol + 1]);
                if (RELU) { v0 = fmaxf(v0, 0.f); v1 = fmaxf(v1, 0.f); }
                *reinterpret_cast<float2*>(&C[(size_t)grow * 256 + gcol]) =
                    make_float2(v0, v1);
            }
        }
    }
}

// ---------------- SPMM: one warp per dst node, float4 lanes -----------------
template<int W>  // 128 or 256
__global__ __launch_bounds__(256)
void spmm_kernel(const float* __restrict__ t, float* __restrict__ out) {
    int wid = threadIdx.x >> 5, lane = threadIdx.x & 31;
    int node = blockIdx.x * 8 + wid;
    if (node >= N_NODES) return;
    int start = g_rowptr[node];
    int end   = g_rowptr[node + 1];

    float4 acc0 = make_float4(0.f, 0.f, 0.f, 0.f);
    float4 acc1 = make_float4(0.f, 0.f, 0.f, 0.f);

    for (int base = start; base < end; base += 32) {
        int idx = base + lane;
        int   s  = (idx < end) ? g_csr_src[idx] : 0;
        float wv = (idx < end) ? g_csr_w[idx]   : 0.f;
        int cnt = min(32, end - base);
        for (int i = 0; i < cnt; i++) {
            int   ss = __shfl_sync(0xffffffffu, s, i);
            float ww = __shfl_sync(0xffffffffu, wv, i);
            const float4* row = reinterpret_cast<const float4*>(t + (size_t)ss * W);
            float4 v0 = row[lane];
            acc0.x = fmaf(v0.x, ww, acc0.x); acc0.y = fmaf(v0.y, ww, acc0.y);
            acc0.z = fmaf(v0.z, ww, acc0.z); acc0.w = fmaf(v0.w, ww, acc0.w);
            if (W == 256) {
                float4 v1 = row[lane + 32];
                acc1.x = fmaf(v1.x, ww, acc1.x); acc1.y = fmaf(v1.y, ww, acc1.y);
                acc1.z = fmaf(v1.z, ww, acc1.z); acc1.w = fmaf(v1.w, ww, acc1.w);
            }
        }
    }
    float4* orow = reinterpret_cast<float4*>(out + (size_t)node * W);
    orow[lane] = acc0;
    if (W == 256) orow[lane + 32] = acc1;
}

// ---------------- segment pool (seg_ids are sorted) -------------------------
__global__ __launch_bounds__(HIDDEN)
void pool_kernel(const float* __restrict__ h, const int* __restrict__ seg) {
    int gi = blockIdx.x, tid = threadIdx.x;
    int lo = 0, hi = N_NODES;
    while (lo < hi) { int mid = (lo + hi) >> 1; if (seg[mid] < gi) lo = mid + 1; else hi = mid; }
    int start = lo;
    hi = N_NODES;
    while (lo < hi) { int mid = (lo + hi) >> 1; if (seg[mid] < gi + 1) lo = mid + 1; else hi = mid; }
    int end = lo;
    float a0 = 0.f, a1 = 0.f, a2 = 0.f, a3 = 0.f;
    int i = start;
    for (; i + 3 < end; i += 4) {
        a0 += h[(size_t)(i + 0) * HIDDEN + tid];
        a1 += h[(size_t)(i + 1) * HIDDEN + tid];
        a2 += h[(size_t)(i + 2) * HIDDEN + tid];
        a3 += h[(size_t)(i + 3) * HIDDEN + tid];
    }
    for (; i < end; i++) a0 += h[(size_t)i * HIDDEN + tid];
    g_pool[gi * HIDDEN + tid] = (a0 + a1) + (a2 + a3);
}

// ---------------- dense head: out[g] = relu(pool@Wd+bd) @ Wo + bo -----------
__global__ __launch_bounds__(HIDDEN)
void head_kernel(const float* __restrict__ Wd, const float* __restrict__ bd,
                 const float* __restrict__ Wo, const float* __restrict__ bo,
                 float* __restrict__ out) {
    __shared__ float s_g[HIDDEN];
    __shared__ float s_red[HIDDEN];
    int gi = blockIdx.x, j = threadIdx.x;
    s_g[j] = g_pool[gi * HIDDEN + j];
    __syncthreads();
    float acc = bd[j];
    #pragma unroll 8
    for (int k = 0; k < HIDDEN; k++)
        acc += s_g[k] * Wd[k * HIDDEN + j];
    acc = fmaxf(acc, 0.f);
    s_red[j] = acc * Wo[j];
    __syncthreads();
    for (int s = HIDDEN / 2; s > 0; s >>= 1) {
        if (j < s) s_red[j] += s_red[j + s];
        __syncthreads();
    }
    if (j == 0) out[gi] = s_red[0] + bo[0];
}

// ---------------- launch ----------------------------------------------------
extern "C" void kernel_launch(void* const* d_in, const int* in_sizes, int n_in,
                              void* d_out, int out_size) {
    const float* x    = (const float*)d_in[0];
    const int*   esrc = (const int*)  d_in[1];
    const int*   edst = (const int*)  d_in[2];
    const float* ew   = (const float*)d_in[3];
    const int*   seg  = (const int*)  d_in[4];
    const float* W1   = (const float*)d_in[5];
    const float* b1   = (const float*)d_in[6];
    const float* W2   = (const float*)d_in[7];
    const float* b2   = (const float*)d_in[8];
    const float* Wd   = (const float*)d_in[9];
    const float* bd   = (const float*)d_in[10];
    const float* Wo   = (const float*)d_in[11];
    const float* bo   = (const float*)d_in[12];
    float* out = (float*)d_out;

    float* bufA; cudaGetSymbolAddress((void**)&bufA, g_bufA);
    float* bufB; cudaGetSymbolAddress((void**)&bufB, g_bufB);
    float* Wt1;  cudaGetSymbolAddress((void**)&Wt1,  g_Wt1);
    float* Wt2;  cudaGetSymbolAddress((void**)&Wt2,  g_Wt2);

    // --- weight transposes (tiny) ---
    {
        dim3 blk(32, 8);
        dim3 g1(HIDDEN / 32, F_IN / 32);
        transpose_kernel<<<g1, blk>>>(W1, Wt1, F_IN, HIDDEN);
        dim3 g2(HIDDEN / 32, HIDDEN / 32);
        transpose_kernel<<<g2, blk>>>(W2, Wt2, HIDDEN, HIDDEN);
    }

    // --- CSR build (by destination) ---
    zero_rowptr_kernel<<<(N_NODES + 256) / 256, 256>>>();
    count_kernel<<<(N_EDGES + 255) / 256, 256>>>(edst);
    scan_kernel<<<1, 1024>>>();
    fill_init_kernel<<<(N_NODES + 255) / 256, 256>>>();
    scatter_kernel<<<(N_EDGES + 255) / 256, 256>>>(esrc, edst, ew);

    const int n_mtiles = (N_NODES + 127) / 128;
    const size_t smem_bytes = (2 * 128 * 32 + 2 * 64 * 32) * sizeof(uint32_t); // 48KB

    // --- layer 1: s0 = spmm(x) [N,128]; h1 = relu(s0 @ W1 + b1) ---
    spmm_kernel<F_IN><<<(N_NODES + 7) / 8, 256>>>(x, bufA);
    mma_gemm_kernel<F_IN, true><<<dim3(4, n_mtiles), 256, smem_bytes>>>(
        bufA, Wt1, b1, bufB, N_NODES);

    // --- layer 2: s1 = spmm(h1) [N,256]; h2 = relu(s1 @ W2 + b2) ---
    spmm_kernel<HIDDEN><<<(N_NODES + 7) / 8, 256>>>(bufB, bufA);
    mma_gemm_kernel<HIDDEN, true><<<dim3(4, n_mtiles), 256, smem_bytes>>>(
        bufA, Wt2, b2, bufB, N_NODES);

    // --- pool + head ---
    pool_kernel<<<N_GRAPHS, HIDDEN>>>(bufB, seg);
    head_kernel<<<N_GRAPHS, HIDDEN>>>(Wd, bd, Wo, bo, out);
}